// round 17
// baseline (speedup 1.0000x reference)
#include <cuda_runtime.h>
#include <cuda_bf16.h>
#include <cstdint>

// Problem constants: B*C = 16, L = 128, N = 48
#define BC 16

// Scratch (device globals; allocation in kernel_launch is forbidden)
__device__ float g_bufA[(size_t)BC * 16384 * 48];
__device__ float g_bufB[(size_t)BC * 6144  * 48];
__device__ float g_bufC[(size_t)BC * 2304  * 48];

// Precomputed W fragments (mma.m16n8k16 B-operand layout), bf16 hi/lo split.
__device__ uint2 g_wfHi[6][1536];
__device__ uint2 g_wfLo[6][1536];

__device__ __forceinline__ float bf16hi(float v) {
    return __bfloat162float(__float2bfloat16_rn(v));
}
__device__ __forceinline__ uint32_t packbf2(float a, float b) {
    __nv_bfloat162 t = __floats2bfloat162_rn(a, b);
    return *reinterpret_cast<uint32_t*>(&t);
}

__device__ __forceinline__ void mma_bf16(float d[4], const uint4& a, const uint2& b) {
    asm volatile(
        "mma.sync.aligned.m16n8k16.row.col.f32.bf16.bf16.f32 "
        "{%0,%1,%2,%3}, {%4,%5,%6,%7}, {%8,%9}, {%0,%1,%2,%3};"
        : "+f"(d[0]), "+f"(d[1]), "+f"(d[2]), "+f"(d[3])
        : "r"(a.x), "r"(a.y), "r"(a.z), "r"(a.w), "r"(b.x), "r"(b.y));
}

// ldmatrix x4 transposed: builds m16n8k16 A-fragment from [k][j] bf16 smem.
__device__ __forceinline__ uint4 ldsm_t(uint32_t addr) {
    uint4 r;
    asm volatile(
        "ldmatrix.sync.aligned.m8n8.x4.trans.shared.b16 {%0,%1,%2,%3}, [%4];"
        : "=r"(r.x), "=r"(r.y), "=r"(r.z), "=r"(r.w) : "r"(addr));
    return r;
}

// Build m16n8k16 B-fragment layout for all 6 weight matrices (bf16 hi/lo split).
__global__ void prep_wfrag(const float* __restrict__ W0, const float* __restrict__ W1,
                           const float* __restrict__ W2, const float* __restrict__ W3,
                           const float* __restrict__ W4, const float* __restrict__ W5)
{
    const int m = blockIdx.y;
    const float* W = (m==0)?W0:(m==1)?W1:(m==2)?W2:(m==3)?W3:(m==4)?W4:W5;
    const int M   = (m < 3) ? 48 : 128;
    const int NMT = M / 8;
    const int t = blockIdx.x * blockDim.x + threadIdx.x;   // 0..1535
    const int rem  = t % (NMT * 32);
    const int kc   = t / (NMT * 32);
    const int mt   = rem / 32;
    const int lane = rem % 32;
    const int tq = lane & 3, gid = lane >> 2;
    const int k0 = kc * 16 + 2 * tq;
    const int c  = mt * 8 + gid;
    const float w00 = W[(k0    ) * M + c], w01 = W[(k0 + 1) * M + c];
    const float w08 = W[(k0 + 8) * M + c], w09 = W[(k0 + 9) * M + c];
    const float h00 = bf16hi(w00), h01 = bf16hi(w01);
    const float h08 = bf16hi(w08), h09 = bf16hi(w09);
    g_wfHi[m][t] = make_uint2(packbf2(h00, h01), packbf2(h08, h09));
    g_wfLo[m][t] = make_uint2(packbf2(w00 - h00, w01 - h01), packbf2(w08 - h08, w09 - h09));
}

// out[b][j][m] = sum_k in[b][k][j] * W[k][m]   (bf16 2-split, 3 products, m16n8k16)
// MWARPS m-warps x JW j-groups; each warp: NSL strips x NTILE 8-wide m-tiles.
// A panel staged COALESCED (LDG.128) into [k][j] bf16 hi/lo smem (PJ pad).
// A-fragments SOFTWARE-PIPELINED: (kc,sl+1)'s ldsm pair is in flight while
// (kc,sl)'s HMMA batch executes (double-buffered fragment regs).
// B fragments double-buffered over kc.
template<int K, int M, int NW, int NS, int MWARPS, int NTILE, int MINB>
__global__ void __launch_bounds__(NW * 32, MINB) mma_stage(
    const float* __restrict__ in, const uint2* __restrict__ wHi,
    const uint2* __restrict__ wLo, float* __restrict__ out, int J)
{
    constexpr int KC  = K / 16;
    constexpr int NMT = M / 8;
    constexpr int BJ  = NS * 16;
    constexpr int PJ  = BJ + 8;            // bf16 pad: conflict-spread rows
    constexpr int JW  = NW / MWARPS;
    constexpr int NSL = NS / JW;
    constexpr int NT  = NW * 32;

    __shared__ __nv_bfloat16 AsH[K * PJ];
    __shared__ __nv_bfloat16 AsL[K * PJ];

    const int tid  = threadIdx.x;
    const int lane = tid & 31, warp = tid >> 5;
    const int tq = lane & 3, gid = lane >> 2;
    const int b  = blockIdx.z;
    const int j0 = blockIdx.x * BJ;
    const int mt0 = (warp % MWARPS) * NTILE;
    const int s0  = (warp / MWARPS) * NSL;

    // ---- preload first B fragments (overlaps staging) ----
    uint2 bh[2][NTILE], bl[2][NTILE];
#pragma unroll
    for (int nt = 0; nt < NTILE; nt++) {
        bh[0][nt] = __ldg(&wHi[(mt0 + nt) * 32 + lane]);
        bl[0][nt] = __ldg(&wLo[(mt0 + nt) * 32 + lane]);
    }

    // ---- stage A panel: coalesced float4 loads, hi/lo bf16 split, STS.64 ----
    const float* inb = in + (size_t)b * K * J + j0;
#pragma unroll
    for (int idx = tid; idx < K * BJ / 4; idx += NT) {
        const int k  = idx / (BJ / 4);
        const int jq = (idx % (BJ / 4)) * 4;
        const float4 v = *reinterpret_cast<const float4*>(&inb[(size_t)k * J + jq]);
        const float h0 = bf16hi(v.x), h1 = bf16hi(v.y), h2 = bf16hi(v.z), h3 = bf16hi(v.w);
        *reinterpret_cast<uint2*>(&AsH[k * PJ + jq]) =
            make_uint2(packbf2(h0, h1), packbf2(h2, h3));
        *reinterpret_cast<uint2*>(&AsL[k * PJ + jq]) =
            make_uint2(packbf2(v.x - h0, v.y - h1), packbf2(v.z - h2, v.w - h3));
    }
    __syncthreads();

    // per-lane ldmatrix base offset (bytes) within a (kc, s) tile
    const uint32_t aH0 = (uint32_t)__cvta_generic_to_shared(AsH);
    const uint32_t aL0 = (uint32_t)__cvta_generic_to_shared(AsL);
    const uint32_t lrow = ((lane & 16) >> 1) + (lane & 7);   // k row within tile
    const uint32_t lcol = (lane & 8);                        // j col within tile
    const uint32_t lofs = 2 * (lrow * PJ + lcol);

    float acc[NSL][NTILE][4];
#pragma unroll
    for (int sl = 0; sl < NSL; sl++)
#pragma unroll
        for (int nt = 0; nt < NTILE; nt++)
#pragma unroll
            for (int r = 0; r < 4; r++) acc[sl][nt][r] = 0.0f;

    // ---- kc x sl loop with pipelined A-fragments ----
    uint4 fah[2], fal[2];
    {
        const uint32_t toff0 = 2 * (s0 * 16) + lofs;
        fah[0] = ldsm_t(aH0 + toff0);
        fal[0] = ldsm_t(aL0 + toff0);
    }

#pragma unroll
    for (int kc = 0; kc < KC; kc++) {
        const int curB = kc & 1, nxtB = curB ^ 1;
        if (kc + 1 < KC) {
#pragma unroll
            for (int nt = 0; nt < NTILE; nt++) {
                bh[nxtB][nt] = __ldg(&wHi[((kc + 1) * NMT + mt0 + nt) * 32 + lane]);
                bl[nxtB][nt] = __ldg(&wLo[((kc + 1) * NMT + mt0 + nt) * 32 + lane]);
            }
        }
#pragma unroll
        for (int sl = 0; sl < NSL; sl++) {
            const int cur = (kc * NSL + sl) & 1;
            // prefetch next fragment (in flight during HMMA batch below)
            int nkc = kc, nsl = sl + 1;
            if (nsl == NSL) { nsl = 0; nkc = kc + 1; }
            if (nkc < KC) {
                const uint32_t toff = 2 * (nkc * 16 * PJ + (s0 + nsl) * 16) + lofs;
                fah[cur ^ 1] = ldsm_t(aH0 + toff);
                fal[cur ^ 1] = ldsm_t(aL0 + toff);
            }
#pragma unroll
            for (int nt = 0; nt < NTILE; nt++) {
                mma_bf16(acc[sl][nt], fal[cur], bh[curB][nt]);   // small terms first
                mma_bf16(acc[sl][nt], fah[cur], bl[curB][nt]);
                mma_bf16(acc[sl][nt], fah[cur], bh[curB][nt]);
            }
        }
    }

    // ---- write out ----
#pragma unroll
    for (int sl = 0; sl < NSL; sl++) {
        float* op = out + (size_t)b * J * M + (size_t)(j0 + (s0 + sl) * 16 + gid) * M;
#pragma unroll
        for (int nt = 0; nt < NTILE; nt++) {
            const int mc = (mt0 + nt) * 8 + 2 * tq;
            *reinterpret_cast<float2*>(&op[mc]) =
                make_float2(acc[sl][nt][0], acc[sl][nt][1]);
            *reinterpret_cast<float2*>(&op[(size_t)8 * M + mc]) =
                make_float2(acc[sl][nt][2], acc[sl][nt][3]);
        }
    }
}

extern "C" void kernel_launch(void* const* d_in, const int* in_sizes, int n_in,
                              void* d_out, int out_size)
{
    const float* x   = (const float*)d_in[0];
    const float* EN3 = (const float*)d_in[1];
    const float* EN2 = (const float*)d_in[2];
    const float* EN1 = (const float*)d_in[3];
    const float* DE3 = (const float*)d_in[4];
    const float* DE2 = (const float*)d_in[5];
    const float* DE1 = (const float*)d_in[6];
    float* out = (float*)d_out;

    float *bufA, *bufB, *bufC;
    cudaGetSymbolAddress((void**)&bufA, g_bufA);
    cudaGetSymbolAddress((void**)&bufB, g_bufB);
    cudaGetSymbolAddress((void**)&bufC, g_bufC);
    uint2 *wfHi, *wfLo;
    cudaGetSymbolAddress((void**)&wfHi, g_wfHi);
    cudaGetSymbolAddress((void**)&wfLo, g_wfLo);

    prep_wfrag<<<dim3(12, 6), 128>>>(EN3, EN2, EN1, DE3, DE2, DE1);

    // Round-13 stage shapes (139.3us winner) with relaxed reg caps for the
    // fragment pipeline:
    //  Encode: NW=4 (MWARPS=2, NTILE=3, NSL=2), BJ=64, minB=4 (128-reg budget).
    //  Decode: NW=8 (MWARPS=8, NTILE=2, NSL=4), BJ=64, minB=2 (128-reg budget).
    // (single decode ordering == averaged result exactly; mode contractions commute)
    auto enc = mma_stage<128, 48, 4, 4, 2, 3, 4>;
    auto dec = mma_stage<48, 128, 8, 4, 8, 2, 2>;

    // S1: contract d.  x[bc][d][hw]   (J=16384) -> bufA = [bc][h][w][p]
    enc<<<dim3(256, 1, BC), 128>>>(x,    wfHi + 0*1536, wfLo + 0*1536, bufA, 16384);
    // S2: contract h.  bufA[bc][h][wp] (J=6144) -> bufB = [bc][w][p][q]
    enc<<<dim3(96, 1, BC), 128>>>(bufA, wfHi + 1*1536, wfLo + 1*1536, bufB, 6144);
    // S3: contract w.  bufB[bc][w][pq] (J=2304) -> bufC = enc = [bc][p][q][r]
    enc<<<dim3(36, 1, BC), 128>>>(bufB, wfHi + 2*1536, wfLo + 2*1536, bufC, 2304);

    // S4: contract p.  enc[bc][p][qr]  (J=2304) -> bufB = [bc][q][r][d]
    dec<<<dim3(36, 1, BC), 256>>>(bufC, wfHi + 3*1536, wfLo + 3*1536, bufB, 2304);
    // S5: contract q.  bufB[bc][q][rd] (J=6144) -> bufA = [bc][r][d][h]
    dec<<<dim3(96, 1, BC), 256>>>(bufB, wfHi + 4*1536, wfLo + 4*1536, bufA, 6144);
    // S6: contract r.  bufA[bc][r][dh] (J=16384) -> out = [b][c][d][h][w]
    dec<<<dim3(256, 1, BC), 256>>>(bufA, wfHi + 5*1536, wfLo + 5*1536, out, 16384);
}